// round 9
// baseline (speedup 1.0000x reference)
#include <cuda_runtime.h>
#include <math.h>

#define BATCH 8192

// sp layout (per-sample, padded)
#define RS 20            // row stride in floats
#define PS 324           // plane (channel) stride
// sU: [oc]*132 + [ic]*16 + xi
#define UIDX(oc, ic) ((oc) * 132 + (ic) * 16)
// sV: tile-major, stride 20 per tile
#define VT 20

// ---------------------------------------------------------------------------
// Scratch
// ---------------------------------------------------------------------------
__device__ __align__(16) float g_flat[BATCH * 784]; // conv2 output [B,784]
__device__ __align__(16) float g_feat[BATCH * 4];   // fc2 output   [B,4]
__device__ float g_scsh[8];                         // [scale, shift]

// ---------------------------------------------------------------------------
// K-: empty dummies to align ncu's profiled launch (index 3) onto k_conv
// ---------------------------------------------------------------------------
__global__ void k_nop() {}

// ---------------------------------------------------------------------------
// K1: fused conv1(direct)+pool, conv2(Winograd F(2x2,3x3), register-U)+pool.
// 1 sample/block, 224 threads. U in registers (loaded once), V staged fully,
// zero syncs inside the ty loop, output transform via shfl_xor(16).
// ---------------------------------------------------------------------------
__global__ __launch_bounds__(224, 2)
void k_conv(const float* __restrict__ x,
            const float* __restrict__ w1, const float* __restrict__ b1,
            const float* __restrict__ w2, const float* __restrict__ b2) {
    __shared__ __align__(16) float sx[30 * 32];     // padded input (960 f)
    __shared__ __align__(16) float sp[8 * PS];      // conv1 pooled out (2592 f)
    __shared__ __align__(16) float sU[16 * 132];    // Winograd weights (2112 f)
    __shared__ __align__(16) float sV[8 * 49 * VT]; // Winograd inputs (7840 f)
    __shared__ __align__(16) float sflat[784];      // output staging
    __shared__ __align__(16) float sw1p[96];
    __shared__ float sb1[8], sb2[16];

    const int tid = threadIdx.x;
    const int b = blockIdx.x;

    // ---- phase 0: zero + weights (incl. Winograd weight transform) ----
    for (int i = tid; i < 960; i += 224) sx[i] = 0.0f;
    for (int i = tid; i < 8 * PS; i += 224) sp[i] = 0.0f;
    if (tid < 72) sw1p[(tid / 9) * 12 + (tid % 9)] = w1[tid];
    if (tid < 8)  sb1[tid] = b1[tid];
    if (tid < 16) sb2[tid] = b2[tid];
    if (tid < 128) {
        const int oc = tid >> 3, ic = tid & 7;
        const float* gp = &w2[oc * 72 + ic * 9];
        float g[9];
        #pragma unroll
        for (int j = 0; j < 9; j++) g[j] = gp[j];
        float T[4][3];
        #pragma unroll
        for (int c = 0; c < 3; c++) {
            T[0][c] = g[c];
            T[1][c] = (g[c] + g[3 + c] + g[6 + c]) * 0.5f;
            T[2][c] = (g[c] - g[3 + c] + g[6 + c]) * 0.5f;
            T[3][c] = g[6 + c];
        }
        float* up = &sU[UIDX(oc, ic)];
        #pragma unroll
        for (int i = 0; i < 4; i++) {
            up[4 * i + 0] = T[i][0];
            up[4 * i + 1] = (T[i][0] + T[i][1] + T[i][2]) * 0.5f;
            up[4 * i + 2] = (T[i][0] - T[i][1] + T[i][2]) * 0.5f;
            up[4 * i + 3] = T[i][2];
        }
    }
    __syncthreads();

    for (int i = tid; i < 784; i += 224)
        sx[(i / 28 + 1) * 32 + (i % 28 + 1)] = x[b * 784 + i];
    __syncthreads();

    // ---- phase 1: conv1 (1->8) + relu + pool -> sp (direct) ----
    {
        const int oc = tid & 7;
        const int rest = tid >> 3;      // 0..27
        const int y2 = rest % 14;
        const int xh = rest / 14;       // 0..1
        float4 wa = *(const float4*)&sw1p[oc * 12];
        float4 wb = *(const float4*)&sw1p[oc * 12 + 4];
        float4 wc = *(const float4*)&sw1p[oc * 12 + 8];
        const float w[9] = {wa.x, wa.y, wa.z, wa.w, wb.x, wb.y, wb.z, wb.w, wc.x};
        const float bias = sb1[oc];
        const int SH = xh * 2;
        float a0[14], a1[14];
        #pragma unroll
        for (int i2 = 0; i2 < 14; i2++) { a0[i2] = bias; a1[i2] = bias; }

        #pragma unroll
        for (int r = 0; r < 4; r++) {
            float e[20];
            const float* rp = &sx[(2 * y2 + r) * 32 + xh * 12];
            #pragma unroll
            for (int q = 0; q < 5; q++) ((float4*)e)[q] = ((const float4*)rp)[q];
            if (r < 3) {
                #pragma unroll
                for (int xx = 0; xx < 14; xx++) {
                    float a = a0[xx];
                    a = fmaf(e[xx + SH],     w[3 * r],     a);
                    a = fmaf(e[xx + SH + 1], w[3 * r + 1], a);
                    a = fmaf(e[xx + SH + 2], w[3 * r + 2], a);
                    a0[xx] = a;
                }
            }
            if (r >= 1) {
                #pragma unroll
                for (int xx = 0; xx < 14; xx++) {
                    float a = a1[xx];
                    a = fmaf(e[xx + SH],     w[3 * (r - 1)],     a);
                    a = fmaf(e[xx + SH + 1], w[3 * (r - 1) + 1], a);
                    a = fmaf(e[xx + SH + 2], w[3 * (r - 1) + 2], a);
                    a1[xx] = a;
                }
            }
        }
        float* spb = &sp[oc * PS + (y2 + 1) * RS];
        #pragma unroll
        for (int p = 0; p < 7; p++) {
            float a = fmaxf(a0[2 * p], 0.0f);
            a = fmaxf(a, fmaxf(a0[2 * p + 1], 0.0f));
            a = fmaxf(a, fmaxf(a1[2 * p], 0.0f));
            a = fmaxf(a, fmaxf(a1[2 * p + 1], 0.0f));
            spb[xh * 7 + p + 1] = a;
        }
    }
    __syncthreads();

    // ---- phase 2a: input transform for ALL tiles -> sV ----
    for (int i = tid; i < 392; i += 224) {
        const int ic = i / 49;
        const int t = i % 49;
        const int ty = t / 7, tx = t % 7;
        const float* rowp = &sp[ic * PS + (2 * ty) * RS + 2 * tx];
        float d[4][4];
        #pragma unroll
        for (int q = 0; q < 4; q++) {
            float2 lo = *(const float2*)(rowp + q * RS);
            float2 hi = *(const float2*)(rowp + q * RS + 2);
            d[q][0] = lo.x; d[q][1] = lo.y; d[q][2] = hi.x; d[q][3] = hi.y;
        }
        float T[4][4];
        #pragma unroll
        for (int c = 0; c < 4; c++) {
            T[0][c] = d[0][c] - d[2][c];
            T[1][c] = d[1][c] + d[2][c];
            T[2][c] = d[2][c] - d[1][c];
            T[3][c] = d[1][c] - d[3][c];
        }
        float* vp = &sV[(ic * 49 + t) * VT];
        #pragma unroll
        for (int r = 0; r < 4; r++) {
            float4 v;
            v.x = T[r][0] - T[r][2];
            v.y = T[r][1] + T[r][2];
            v.z = T[r][2] - T[r][1];
            v.w = T[r][1] - T[r][3];
            *(float4*)(vp + 4 * r) = v;
        }
    }
    __syncthreads();

    // ---- phase 2b: elementwise + output transform (register U) ----
    // thread = oc + 16*h + 32*tx ; owns xi-rows {h, h+2}
    {
        const int oc = tid & 15;
        const int h = (tid >> 4) & 1;
        const int tx = tid >> 5;        // 0..6
        const float bias2 = sb2[oc];

        float uu[64];
        #pragma unroll
        for (int ic = 0; ic < 8; ic++) {
            const float* up = &sU[UIDX(oc, ic)];
            float4 a = *(const float4*)(up + 4 * h);      // row h
            float4 c = *(const float4*)(up + 4 * h + 8);  // row h+2
            uu[ic * 8 + 0] = a.x; uu[ic * 8 + 1] = a.y;
            uu[ic * 8 + 2] = a.z; uu[ic * 8 + 3] = a.w;
            uu[ic * 8 + 4] = c.x; uu[ic * 8 + 5] = c.y;
            uu[ic * 8 + 6] = c.z; uu[ic * 8 + 7] = c.w;
        }

        for (int ty = 0; ty < 7; ty++) {
            float M[8];
            #pragma unroll
            for (int k = 0; k < 8; k++) M[k] = 0.0f;

            #pragma unroll
            for (int ic = 0; ic < 8; ic++) {
                const float* vp = &sV[(ic * 49 + ty * 7 + tx) * VT];
                float4 va = *(const float4*)(vp + 4 * h);
                float4 vb = *(const float4*)(vp + 4 * h + 8);
                M[0] = fmaf(uu[ic * 8 + 0], va.x, M[0]);
                M[1] = fmaf(uu[ic * 8 + 1], va.y, M[1]);
                M[2] = fmaf(uu[ic * 8 + 2], va.z, M[2]);
                M[3] = fmaf(uu[ic * 8 + 3], va.w, M[3]);
                M[4] = fmaf(uu[ic * 8 + 4], vb.x, M[4]);
                M[5] = fmaf(uu[ic * 8 + 5], vb.y, M[5]);
                M[6] = fmaf(uu[ic * 8 + 6], vb.z, M[6]);
                M[7] = fmaf(uu[ic * 8 + 7], vb.w, M[7]);
            }
            // column transform on owned rows (rA = h, rB = h+2)
            float c0A = M[0] + M[1] + M[2];
            float c1A = M[1] - M[2] - M[3];
            float c0B = M[4] + M[5] + M[6];
            float c1B = M[5] - M[6] - M[7];
            // partial row-combines
            float p00, p01, p10, p11;
            if (h == 0) {   // rows 0,2
                p00 = c0A + c0B;   // n0(0)+n0(2)
                p01 = c1A + c1B;
                p10 = -c0B;        // -n0(2)
                p11 = -c1B;
            } else {        // rows 1,3
                p00 = c0A;         // n0(1)
                p01 = c1A;
                p10 = c0A - c0B;   // n0(1)-n0(3)
                p11 = c1A - c1B;
            }
            p00 += __shfl_xor_sync(0xffffffff, p00, 16);
            p01 += __shfl_xor_sync(0xffffffff, p01, 16);
            p10 += __shfl_xor_sync(0xffffffff, p10, 16);
            p11 += __shfl_xor_sync(0xffffffff, p11, 16);
            if (h == 0) {
                float a = fmaxf(p00 + bias2, 0.0f);
                a = fmaxf(a, fmaxf(p01 + bias2, 0.0f));
                a = fmaxf(a, fmaxf(p10 + bias2, 0.0f));
                a = fmaxf(a, fmaxf(p11 + bias2, 0.0f));
                sflat[oc * 49 + ty * 7 + tx] = a;
            }
        }
    }
    __syncthreads();

    // ---- coalesced write ----
    if (tid < 196)
        ((float4*)&g_flat[b * 784])[tid] = ((const float4*)sflat)[tid];
}

// ---------------------------------------------------------------------------
// K2: FC1(784->64)+relu + FC2(64->4), tiled GEMM. 64 samples/block.
// ---------------------------------------------------------------------------
#define FC_STRIDE 60
__global__ __launch_bounds__(256)
void k_fc(const float* __restrict__ fc1_w, const float* __restrict__ fc1_b,
          const float* __restrict__ fc2_w, const float* __restrict__ fc2_b) {
    __shared__ __align__(16) float sAW[2 * 64 * FC_STRIDE];
    __shared__ float sw2[256];
    float* sA = sAW;
    float* sW = sAW + 64 * FC_STRIDE;

    const int tid = threadIdx.x;
    const int s0 = blockIdx.x * 64;
    const int jj = tid & 31;
    const int ss = tid >> 5;

    for (int i = tid; i < 256; i += 256) sw2[i] = fc2_w[i];

    float acc[2][8];
    #pragma unroll
    for (int u = 0; u < 8; u++) { acc[0][u] = 0.0f; acc[1][u] = 0.0f; }

    for (int kt = 0; kt < 784; kt += 56) {
        __syncthreads();
        #pragma unroll
        for (int i = tid; i < 64 * 14; i += 256) {
            int r = i / 14, q = i % 14;
            ((float4*)&sA[r * FC_STRIDE])[q] =
                *(const float4*)&g_flat[(s0 + r) * 784 + kt + q * 4];
            ((float4*)&sW[r * FC_STRIDE])[q] =
                *(const float4*)&fc1_w[r * 784 + kt + q * 4];
        }
        __syncthreads();
        #pragma unroll
        for (int k4 = 0; k4 < 14; k4++) {
            float4 w0 = *(const float4*)&sW[jj * FC_STRIDE + k4 * 4];
            float4 w1 = *(const float4*)&sW[(jj + 32) * FC_STRIDE + k4 * 4];
            #pragma unroll
            for (int u = 0; u < 8; u++) {
                float4 a = *(const float4*)&sA[(ss * 8 + u) * FC_STRIDE + k4 * 4];
                float t0 = acc[0][u], t1 = acc[1][u];
                t0 = fmaf(a.x, w0.x, t0); t1 = fmaf(a.x, w1.x, t1);
                t0 = fmaf(a.y, w0.y, t0); t1 = fmaf(a.y, w1.y, t1);
                t0 = fmaf(a.z, w0.z, t0); t1 = fmaf(a.z, w1.z, t1);
                t0 = fmaf(a.w, w0.w, t0); t1 = fmaf(a.w, w1.w, t1);
                acc[0][u] = t0; acc[1][u] = t1;
            }
        }
    }

    __syncthreads();
    float* sh = sAW;
    const float bj0 = fc1_b[jj], bj1 = fc1_b[jj + 32];
    #pragma unroll
    for (int u = 0; u < 8; u++) {
        sh[(ss * 8 + u) * 65 + jj]      = fmaxf(acc[0][u] + bj0, 0.0f);
        sh[(ss * 8 + u) * 65 + jj + 32] = fmaxf(acc[1][u] + bj1, 0.0f);
    }
    __syncthreads();

    {
        const int s = tid >> 2, c = tid & 3;
        float a = fc2_b[c];
        const float* hp = &sh[s * 65];
        const float* wc = &sw2[c * 64];
        #pragma unroll
        for (int j = 0; j < 64; j++) a = fmaf(hp[j], wc[j], a);
        g_feat[(s0 + s) * 4 + c] = a;
    }
}

// ---------------------------------------------------------------------------
// K3: batch mean/var -> scale/shift
// ---------------------------------------------------------------------------
__global__ void k_stats(const float* __restrict__ bn_g,
                        const float* __restrict__ bn_b) {
    __shared__ double ss[256][8];
    const int tid = threadIdx.x;
    double sum[4] = {0, 0, 0, 0}, sq[4] = {0, 0, 0, 0};
    for (int s = tid; s < BATCH; s += 256) {
        float4 f = ((const float4*)g_feat)[s];
        double v;
        v = (double)f.x; sum[0] += v; sq[0] += v * v;
        v = (double)f.y; sum[1] += v; sq[1] += v * v;
        v = (double)f.z; sum[2] += v; sq[2] += v * v;
        v = (double)f.w; sum[3] += v; sq[3] += v * v;
    }
    #pragma unroll
    for (int c = 0; c < 4; c++) { ss[tid][c] = sum[c]; ss[tid][4 + c] = sq[c]; }
    __syncthreads();
    for (int off = 128; off >= 1; off >>= 1) {
        if (tid < off) {
            #pragma unroll
            for (int k = 0; k < 8; k++) ss[tid][k] += ss[tid + off][k];
        }
        __syncthreads();
    }
    if (tid < 4) {
        double m = ss[0][tid] / (double)BATCH;
        double var = ss[0][4 + tid] / (double)BATCH - m * m;
        float scale = (float)((double)bn_g[tid] / sqrt(var + 1e-5));
        float shift = bn_b[tid] - (float)m * scale;
        g_scsh[tid] = scale;
        g_scsh[4 + tid] = shift;
    }
}

// ---------------------------------------------------------------------------
// K4: quantum state-vector sim + PauliZ measurement
// ---------------------------------------------------------------------------
template <int STR>
__device__ __forceinline__ void rot_rx(float* sr, float* si, float c, float s) {
    #pragma unroll
    for (int k = 0; k < 16; k++) {
        if (k & STR) continue;
        int k1 = k | STR;
        float ar0 = sr[k], ai0 = si[k], ar1 = sr[k1], ai1 = si[k1];
        sr[k]  = c * ar0 + s * ai1;
        si[k]  = c * ai0 - s * ar1;
        sr[k1] = s * ai0 + c * ar1;
        si[k1] = -s * ar0 + c * ai1;
    }
}

template <int STR>
__device__ __forceinline__ void rot_ry(float* sr, float* si, float c, float s) {
    #pragma unroll
    for (int k = 0; k < 16; k++) {
        if (k & STR) continue;
        int k1 = k | STR;
        float ar0 = sr[k], ai0 = si[k], ar1 = sr[k1], ai1 = si[k1];
        sr[k]  = c * ar0 - s * ar1;
        si[k]  = c * ai0 - s * ai1;
        sr[k1] = s * ar0 + c * ar1;
        si[k1] = s * ai0 + c * ai1;
    }
}

template <int STR>
__device__ __forceinline__ void rot_rz(float* sr, float* si, float c, float s) {
    #pragma unroll
    for (int k = 0; k < 16; k++) {
        float ar = sr[k], ai = si[k];
        if (k & STR) { sr[k] = c * ar - s * ai; si[k] = c * ai + s * ar; }
        else         { sr[k] = c * ar + s * ai; si[k] = c * ai - s * ar; }
    }
}

__device__ __forceinline__ void cnot_c3_t0(float* sr, float* si) {
    #pragma unroll
    for (int k = 1; k < 8; k += 2) {
        int k1 = k | 8;
        float tr = sr[k], ti = si[k];
        sr[k] = sr[k1]; si[k] = si[k1];
        sr[k1] = tr;    si[k1] = ti;
    }
}

__global__ void k_quantum(const float* __restrict__ rl_params,
                          float* __restrict__ out) {
    __shared__ float gc[23], gs[23];
    const int tid = threadIdx.x;
    if (tid < 23) {
        float t = rl_params[tid] * 0.5f;
        gc[tid] = cosf(t);
        gs[tid] = sinf(t);
    }
    __syncthreads();

    const int b = blockIdx.x * blockDim.x + tid;
    if (b >= BATCH) return;

    float sr[16], si[16];
    #pragma unroll
    for (int k = 0; k < 16; k++) { sr[k] = 0.0f; si[k] = 0.0f; }
    sr[0] = 1.0f;

    float4 f4 = ((const float4*)g_feat)[b];
    {
        float f, s, c;
        f = (f4.x * g_scsh[0] + g_scsh[4]) * 0.5f; s = sinf(f); c = cosf(f);
        rot_rx<8>(sr, si, c, s);
        f = (f4.y * g_scsh[1] + g_scsh[5]) * 0.5f; s = sinf(f); c = cosf(f);
        rot_rx<4>(sr, si, c, s);
        f = (f4.z * g_scsh[2] + g_scsh[6]) * 0.5f; s = sinf(f); c = cosf(f);
        rot_rx<2>(sr, si, c, s);
        f = (f4.w * g_scsh[3] + g_scsh[7]) * 0.5f; s = sinf(f); c = cosf(f);
        rot_rx<1>(sr, si, c, s);
    }

    #pragma unroll
    for (int r = 0; r < 7; r++) {
        rot_rx<8>(sr, si, gc[3 * r],     gs[3 * r]);
        rot_ry<4>(sr, si, gc[3 * r + 1], gs[3 * r + 1]);
        rot_rz<2>(sr, si, gc[3 * r + 2], gs[3 * r + 2]);
        cnot_c3_t0(sr, si);
    }
    rot_rx<8>(sr, si, gc[21], gs[21]);
    rot_ry<4>(sr, si, gc[22], gs[22]);

    float p[16];
    #pragma unroll
    for (int k = 0; k < 16; k++) p[k] = sr[k] * sr[k] + si[k] * si[k];
    #pragma unroll
    for (int w = 0; w < 4; w++) {
        int str = 8 >> w;
        float acc = 0.0f;
        #pragma unroll
        for (int k = 0; k < 16; k++) acc += (k & str) ? -p[k] : p[k];
        out[b * 4 + w] = acc;
    }
}

// ---------------------------------------------------------------------------
// Launch (3 dummies first so ncu's profiled launch, index 3, is k_conv)
// ---------------------------------------------------------------------------
extern "C" void kernel_launch(void* const* d_in, const int* in_sizes, int n_in,
                              void* d_out, int out_size) {
    const float* x       = (const float*)d_in[0];
    const float* conv1_w = (const float*)d_in[1];
    const float* conv1_b = (const float*)d_in[2];
    const float* conv2_w = (const float*)d_in[3];
    const float* conv2_b = (const float*)d_in[4];
    const float* fc1_w   = (const float*)d_in[5];
    const float* fc1_b   = (const float*)d_in[6];
    const float* fc2_w   = (const float*)d_in[7];
    const float* fc2_b   = (const float*)d_in[8];
    const float* bn_g    = (const float*)d_in[9];
    const float* bn_b    = (const float*)d_in[10];
    const float* rl      = (const float*)d_in[11];
    float* out = (float*)d_out;

    k_nop<<<1, 32>>>();
    k_nop<<<1, 32>>>();
    k_nop<<<1, 32>>>();
    k_conv<<<BATCH, 224>>>(x, conv1_w, conv1_b, conv2_w, conv2_b);
    k_fc<<<BATCH / 64, 256>>>(fc1_w, fc1_b, fc2_w, fc2_b);
    k_stats<<<1, 256>>>(bn_g, bn_b);
    k_quantum<<<BATCH / 256, 256>>>(rl, out);
}

// round 10
// speedup vs baseline: 1.4951x; 1.4951x over previous
#include <cuda_runtime.h>
#include <math.h>

#define BATCH 8192

// sp layout constants (bank-conflict-free padded layout)
#define RS 20            // row stride in floats
#define PS 324           // plane (channel) stride
#define SS (8 * PS)      // sample stride: 2592 floats

// ---------------------------------------------------------------------------
// Scratch
// ---------------------------------------------------------------------------
__device__ __align__(16) float g_flat[BATCH * 784]; // conv2 output [B,784]
__device__ __align__(16) float g_feat[BATCH * 4];   // fc2 output   [B,4]
__device__ float g_scsh[8];                         // [scale, shift]

// ---------------------------------------------------------------------------
// K-: empty dummies (2) so ncu's profiled launch (index 3) is k_fc
// ---------------------------------------------------------------------------
__global__ void k_nop() {}

// ---------------------------------------------------------------------------
// K1: fused conv1+pool, conv2+pool. 2 samples/block, 224 threads (R7-proven,
// at the scalar-FFMA wall). All inner loads LDS.128; coalesced STG.128 out.
// ---------------------------------------------------------------------------
__global__ __launch_bounds__(224, 4)
void k_conv(const float* __restrict__ x,
            const float* __restrict__ w1, const float* __restrict__ b1,
            const float* __restrict__ w2, const float* __restrict__ b2) {
    __shared__ __align__(16) float sx[2][30][32];   // padded input (1920 f)
    __shared__ __align__(16) float sp[2 * SS];      // conv1 pooled out (5184 f)
    __shared__ __align__(16) float sw1p[96];        // conv1 w, [oc][12]
    __shared__ __align__(16) float sw2p[1600];      // conv2 w, [oc]*100 + [ic]*12
    __shared__ __align__(16) float sflat[2 * 784];  // output staging
    __shared__ float sb1[8], sb2[16];

    const int tid = threadIdx.x;
    const int b0 = blockIdx.x * 2;

    for (int i = tid; i < 1920; i += 224) ((float*)sx)[i] = 0.0f;
    for (int i = tid; i < 2 * SS; i += 224) sp[i] = 0.0f;
    for (int i = tid; i < 1152; i += 224) {
        int oc = i / 72, rem = i % 72, ic = rem / 9, j = rem % 9;
        sw2p[oc * 100 + ic * 12 + j] = w2[i];
    }
    if (tid < 72) sw1p[(tid / 9) * 12 + (tid % 9)] = w1[tid];
    if (tid < 8)  sb1[tid] = b1[tid];
    if (tid < 16) sb2[tid] = b2[tid];
    __syncthreads();

    for (int i = tid; i < 2 * 784; i += 224) {
        int s = i / 784, r = i % 784;
        sx[s][r / 28 + 1][r % 28 + 1] = x[(b0 + s) * 784 + r];
    }
    __syncthreads();

    // -------- conv1 (1->8) + relu + pool -> sp --------
    {
        const int oc = tid & 7;
        const int rest = tid >> 3;      // 0..27
        const int y2 = rest % 14;
        const int s = rest / 14;
        float4 wa = *(const float4*)&sw1p[oc * 12];
        float4 wb = *(const float4*)&sw1p[oc * 12 + 4];
        float4 wc = *(const float4*)&sw1p[oc * 12 + 8];
        const float w[9] = {wa.x, wa.y, wa.z, wa.w, wb.x, wb.y, wb.z, wb.w, wc.x};
        const float bias = sb1[oc];
        float* spb = &sp[s * SS + oc * PS + (y2 + 1) * RS];

        #pragma unroll
        for (int xh = 0; xh < 2; xh++) {
            const int SH = xh * 2;
            float a0[14], a1[14];
            #pragma unroll
            for (int i2 = 0; i2 < 14; i2++) { a0[i2] = bias; a1[i2] = bias; }

            #pragma unroll
            for (int r = 0; r < 4; r++) {
                float e[20];
                const float* rp = &sx[s][2 * y2 + r][xh * 12];
                #pragma unroll
                for (int q = 0; q < 5; q++) ((float4*)e)[q] = ((const float4*)rp)[q];
                if (r < 3) {
                    #pragma unroll
                    for (int xx = 0; xx < 14; xx++) {
                        float a = a0[xx];
                        a = fmaf(e[xx + SH],     w[3 * r],     a);
                        a = fmaf(e[xx + SH + 1], w[3 * r + 1], a);
                        a = fmaf(e[xx + SH + 2], w[3 * r + 2], a);
                        a0[xx] = a;
                    }
                }
                if (r >= 1) {
                    #pragma unroll
                    for (int xx = 0; xx < 14; xx++) {
                        float a = a1[xx];
                        a = fmaf(e[xx + SH],     w[3 * (r - 1)],     a);
                        a = fmaf(e[xx + SH + 1], w[3 * (r - 1) + 1], a);
                        a = fmaf(e[xx + SH + 2], w[3 * (r - 1) + 2], a);
                        a1[xx] = a;
                    }
                }
            }
            #pragma unroll
            for (int p = 0; p < 7; p++) {
                float a = fmaxf(a0[2 * p], 0.0f);
                a = fmaxf(a, fmaxf(a0[2 * p + 1], 0.0f));
                a = fmaxf(a, fmaxf(a1[2 * p], 0.0f));
                a = fmaxf(a, fmaxf(a1[2 * p + 1], 0.0f));
                spb[xh * 7 + p + 1] = a;
            }
        }
    }
    __syncthreads();

    // -------- conv2 (8->16) + relu + pool -> sflat -> g_flat --------
    {
        const int oc = tid & 15;
        const int rest = tid >> 4;     // 0..13
        const int y2 = rest % 7;
        const int s = rest / 7;
        const float bias = sb2[oc];
        float acc0[14], acc1[14];
        #pragma unroll
        for (int i2 = 0; i2 < 14; i2++) { acc0[i2] = bias; acc1[i2] = bias; }

        #pragma unroll
        for (int ic = 0; ic < 8; ic++) {
            const float* wp = &sw2p[oc * 100 + ic * 12];
            float4 wa = *(const float4*)(wp);
            float4 wb = *(const float4*)(wp + 4);
            float4 wc = *(const float4*)(wp + 8);
            const float w[9] = {wa.x, wa.y, wa.z, wa.w, wb.x, wb.y, wb.z, wb.w, wc.x};

            const float* rowp = &sp[s * SS + ic * PS + (2 * y2) * RS];
            #pragma unroll
            for (int r = 0; r < 4; r++) {
                float e[16];
                #pragma unroll
                for (int q = 0; q < 4; q++)
                    ((float4*)e)[q] = ((const float4*)(rowp + r * RS))[q];
                if (r < 3) {
                    #pragma unroll
                    for (int xx = 0; xx < 14; xx++) {
                        float a = acc0[xx];
                        a = fmaf(e[xx],     w[3 * r],     a);
                        a = fmaf(e[xx + 1], w[3 * r + 1], a);
                        a = fmaf(e[xx + 2], w[3 * r + 2], a);
                        acc0[xx] = a;
                    }
                }
                if (r >= 1) {
                    #pragma unroll
                    for (int xx = 0; xx < 14; xx++) {
                        float a = acc1[xx];
                        a = fmaf(e[xx],     w[3 * (r - 1)],     a);
                        a = fmaf(e[xx + 1], w[3 * (r - 1) + 1], a);
                        a = fmaf(e[xx + 2], w[3 * (r - 1) + 2], a);
                        acc1[xx] = a;
                    }
                }
            }
        }

        float* stg = &sflat[s * 784 + oc * 49 + y2 * 7];
        #pragma unroll
        for (int p = 0; p < 7; p++) {
            float a = fmaxf(acc0[2 * p], 0.0f);
            a = fmaxf(a, fmaxf(acc0[2 * p + 1], 0.0f));
            a = fmaxf(a, fmaxf(acc1[2 * p], 0.0f));
            a = fmaxf(a, fmaxf(acc1[2 * p + 1], 0.0f));
            stg[p] = a;
        }
    }
    __syncthreads();

    {
        float4* dst = (float4*)&g_flat[b0 * 784];
        const float4* src = (const float4*)sflat;
        for (int i = tid; i < 392; i += 224) dst[i] = src[i];
    }
}

// ---------------------------------------------------------------------------
// K2: FC1(784->64)+relu + FC2(64->4), tiled GEMM. 32 samples/block,
// 256 blocks -> full-chip single resident wave (2 blocks/SM).
// ---------------------------------------------------------------------------
#define FC_STRIDE 60
__global__ __launch_bounds__(256, 2)
void k_fc(const float* __restrict__ fc1_w, const float* __restrict__ fc1_b,
          const float* __restrict__ fc2_w, const float* __restrict__ fc2_b) {
    __shared__ __align__(16) float sAW[96 * FC_STRIDE];  // sA[32*60] | sW[64*60]
    __shared__ float sw2[256];
    float* sA = sAW;
    float* sW = sAW + 32 * FC_STRIDE;

    const int tid = threadIdx.x;
    const int s0 = blockIdx.x * 32;
    const int jj = tid & 31;     // output pair {jj, jj+32}
    const int ss = tid >> 5;     // 0..7, samples ss*4 .. ss*4+3

    if (tid < 256) sw2[tid] = fc2_w[tid];

    float acc[2][4];
    #pragma unroll
    for (int u = 0; u < 4; u++) { acc[0][u] = 0.0f; acc[1][u] = 0.0f; }

    for (int kt = 0; kt < 784; kt += 56) {
        __syncthreads();
        #pragma unroll
        for (int i = tid; i < 32 * 14; i += 256) {
            int r = i / 14, q = i % 14;
            ((float4*)&sA[r * FC_STRIDE])[q] =
                *(const float4*)&g_flat[(s0 + r) * 784 + kt + q * 4];
        }
        #pragma unroll
        for (int i = tid; i < 64 * 14; i += 256) {
            int r = i / 14, q = i % 14;
            ((float4*)&sW[r * FC_STRIDE])[q] =
                *(const float4*)&fc1_w[r * 784 + kt + q * 4];
        }
        __syncthreads();
        #pragma unroll
        for (int k4 = 0; k4 < 14; k4++) {
            float4 w0 = *(const float4*)&sW[jj * FC_STRIDE + k4 * 4];
            float4 w1 = *(const float4*)&sW[(jj + 32) * FC_STRIDE + k4 * 4];
            #pragma unroll
            for (int u = 0; u < 4; u++) {
                float4 a = *(const float4*)&sA[(ss * 4 + u) * FC_STRIDE + k4 * 4];
                float t0 = acc[0][u], t1 = acc[1][u];
                t0 = fmaf(a.x, w0.x, t0); t1 = fmaf(a.x, w1.x, t1);
                t0 = fmaf(a.y, w0.y, t0); t1 = fmaf(a.y, w1.y, t1);
                t0 = fmaf(a.z, w0.z, t0); t1 = fmaf(a.z, w1.z, t1);
                t0 = fmaf(a.w, w0.w, t0); t1 = fmaf(a.w, w1.w, t1);
                acc[0][u] = t0; acc[1][u] = t1;
            }
        }
    }

    __syncthreads();
    float* sh = sAW;   // reuse: 32 samples x stride 65 = 2080 floats
    const float bj0 = fc1_b[jj], bj1 = fc1_b[jj + 32];
    #pragma unroll
    for (int u = 0; u < 4; u++) {
        sh[(ss * 4 + u) * 65 + jj]      = fmaxf(acc[0][u] + bj0, 0.0f);
        sh[(ss * 4 + u) * 65 + jj + 32] = fmaxf(acc[1][u] + bj1, 0.0f);
    }
    __syncthreads();

    if (tid < 128) {
        const int s = tid >> 2, c = tid & 3;
        float a = fc2_b[c];
        const float* hp = &sh[s * 65];
        const float* wc = &sw2[c * 64];
        #pragma unroll
        for (int j = 0; j < 64; j++) a = fmaf(hp[j], wc[j], a);
        g_feat[(s0 + s) * 4 + c] = a;
    }
}

// ---------------------------------------------------------------------------
// K3: batch mean/var -> scale/shift
// ---------------------------------------------------------------------------
__global__ void k_stats(const float* __restrict__ bn_g,
                        const float* __restrict__ bn_b) {
    __shared__ double ss[256][8];
    const int tid = threadIdx.x;
    double sum[4] = {0, 0, 0, 0}, sq[4] = {0, 0, 0, 0};
    for (int s = tid; s < BATCH; s += 256) {
        float4 f = ((const float4*)g_feat)[s];
        double v;
        v = (double)f.x; sum[0] += v; sq[0] += v * v;
        v = (double)f.y; sum[1] += v; sq[1] += v * v;
        v = (double)f.z; sum[2] += v; sq[2] += v * v;
        v = (double)f.w; sum[3] += v; sq[3] += v * v;
    }
    #pragma unroll
    for (int c = 0; c < 4; c++) { ss[tid][c] = sum[c]; ss[tid][4 + c] = sq[c]; }
    __syncthreads();
    for (int off = 128; off >= 1; off >>= 1) {
        if (tid < off) {
            #pragma unroll
            for (int k = 0; k < 8; k++) ss[tid][k] += ss[tid + off][k];
        }
        __syncthreads();
    }
    if (tid < 4) {
        double m = ss[0][tid] / (double)BATCH;
        double var = ss[0][4 + tid] / (double)BATCH - m * m;
        float scale = (float)((double)bn_g[tid] / sqrt(var + 1e-5));
        float shift = bn_b[tid] - (float)m * scale;
        g_scsh[tid] = scale;
        g_scsh[4 + tid] = shift;
    }
}

// ---------------------------------------------------------------------------
// K4: quantum state-vector sim + PauliZ measurement
// ---------------------------------------------------------------------------
template <int STR>
__device__ __forceinline__ void rot_rx(float* sr, float* si, float c, float s) {
    #pragma unroll
    for (int k = 0; k < 16; k++) {
        if (k & STR) continue;
        int k1 = k | STR;
        float ar0 = sr[k], ai0 = si[k], ar1 = sr[k1], ai1 = si[k1];
        sr[k]  = c * ar0 + s * ai1;
        si[k]  = c * ai0 - s * ar1;
        sr[k1] = s * ai0 + c * ar1;
        si[k1] = -s * ar0 + c * ai1;
    }
}

template <int STR>
__device__ __forceinline__ void rot_ry(float* sr, float* si, float c, float s) {
    #pragma unroll
    for (int k = 0; k < 16; k++) {
        if (k & STR) continue;
        int k1 = k | STR;
        float ar0 = sr[k], ai0 = si[k], ar1 = sr[k1], ai1 = si[k1];
        sr[k]  = c * ar0 - s * ar1;
        si[k]  = c * ai0 - s * ai1;
        sr[k1] = s * ar0 + c * ar1;
        si[k1] = s * ai0 + c * ai1;
    }
}

template <int STR>
__device__ __forceinline__ void rot_rz(float* sr, float* si, float c, float s) {
    #pragma unroll
    for (int k = 0; k < 16; k++) {
        float ar = sr[k], ai = si[k];
        if (k & STR) { sr[k] = c * ar - s * ai; si[k] = c * ai + s * ar; }
        else         { sr[k] = c * ar + s * ai; si[k] = c * ai - s * ar; }
    }
}

__device__ __forceinline__ void cnot_c3_t0(float* sr, float* si) {
    #pragma unroll
    for (int k = 1; k < 8; k += 2) {
        int k1 = k | 8;
        float tr = sr[k], ti = si[k];
        sr[k] = sr[k1]; si[k] = si[k1];
        sr[k1] = tr;    si[k1] = ti;
    }
}

__global__ void k_quantum(const float* __restrict__ rl_params,
                          float* __restrict__ out) {
    __shared__ float gc[23], gs[23];
    const int tid = threadIdx.x;
    if (tid < 23) {
        float t = rl_params[tid] * 0.5f;
        gc[tid] = cosf(t);
        gs[tid] = sinf(t);
    }
    __syncthreads();

    const int b = blockIdx.x * blockDim.x + tid;
    if (b >= BATCH) return;

    float sr[16], si[16];
    #pragma unroll
    for (int k = 0; k < 16; k++) { sr[k] = 0.0f; si[k] = 0.0f; }
    sr[0] = 1.0f;

    float4 f4 = ((const float4*)g_feat)[b];
    {
        float f, s, c;
        f = (f4.x * g_scsh[0] + g_scsh[4]) * 0.5f; s = sinf(f); c = cosf(f);
        rot_rx<8>(sr, si, c, s);
        f = (f4.y * g_scsh[1] + g_scsh[5]) * 0.5f; s = sinf(f); c = cosf(f);
        rot_rx<4>(sr, si, c, s);
        f = (f4.z * g_scsh[2] + g_scsh[6]) * 0.5f; s = sinf(f); c = cosf(f);
        rot_rx<2>(sr, si, c, s);
        f = (f4.w * g_scsh[3] + g_scsh[7]) * 0.5f; s = sinf(f); c = cosf(f);
        rot_rx<1>(sr, si, c, s);
    }

    #pragma unroll
    for (int r = 0; r < 7; r++) {
        rot_rx<8>(sr, si, gc[3 * r],     gs[3 * r]);
        rot_ry<4>(sr, si, gc[3 * r + 1], gs[3 * r + 1]);
        rot_rz<2>(sr, si, gc[3 * r + 2], gs[3 * r + 2]);
        cnot_c3_t0(sr, si);
    }
    rot_rx<8>(sr, si, gc[21], gs[21]);
    rot_ry<4>(sr, si, gc[22], gs[22]);

    float p[16];
    #pragma unroll
    for (int k = 0; k < 16; k++) p[k] = sr[k] * sr[k] + si[k] * si[k];
    #pragma unroll
    for (int w = 0; w < 4; w++) {
        int str = 8 >> w;
        float acc = 0.0f;
        #pragma unroll
        for (int k = 0; k < 16; k++) acc += (k & str) ? -p[k] : p[k];
        out[b * 4 + w] = acc;
    }
}

// ---------------------------------------------------------------------------
// Launch (2 dummies first so ncu's profiled launch, index 3, is k_fc)
// ---------------------------------------------------------------------------
extern "C" void kernel_launch(void* const* d_in, const int* in_sizes, int n_in,
                              void* d_out, int out_size) {
    const float* x       = (const float*)d_in[0];
    const float* conv1_w = (const float*)d_in[1];
    const float* conv1_b = (const float*)d_in[2];
    const float* conv2_w = (const float*)d_in[3];
    const float* conv2_b = (const float*)d_in[4];
    const float* fc1_w   = (const float*)d_in[5];
    const float* fc1_b   = (const float*)d_in[6];
    const float* fc2_w   = (const float*)d_in[7];
    const float* fc2_b   = (const float*)d_in[8];
    const float* bn_g    = (const float*)d_in[9];
    const float* bn_b    = (const float*)d_in[10];
    const float* rl      = (const float*)d_in[11];
    float* out = (float*)d_out;

    k_nop<<<1, 32>>>();
    k_nop<<<1, 32>>>();
    k_conv<<<BATCH / 2, 224>>>(x, conv1_w, conv1_b, conv2_w, conv2_b);
    k_fc<<<BATCH / 32, 256>>>(fc1_w, fc1_b, fc2_w, fc2_b);
    k_stats<<<1, 256>>>(bn_g, bn_b);
    k_quantum<<<BATCH / 256, 256>>>(rl, out);
}

// round 11
// speedup vs baseline: 1.5111x; 1.0107x over previous
#include <cuda_runtime.h>
#include <math.h>

#define BATCH 8192

// sp layout constants (bank-conflict-free padded layout)
#define RS 20            // row stride in floats
#define PS 324           // plane (channel) stride
#define SS (8 * PS)      // sample stride: 2592 floats

// ---------------------------------------------------------------------------
// Scratch
// ---------------------------------------------------------------------------
__device__ __align__(16) float g_flat[BATCH * 784]; // conv2 output [B,784]
__device__ __align__(16) float g_feat[BATCH * 4];   // fc2 output   [B,4]
__device__ float g_scsh[8];                         // [scale, shift]

// ---------------------------------------------------------------------------
// K1: fused conv1+pool, conv2+pool. 2 samples/block, 224 threads (R7-proven,
// at the scalar-FFMA wall). All inner loads LDS.128; coalesced STG.128 out.
// ---------------------------------------------------------------------------
__global__ __launch_bounds__(224, 4)
void k_conv(const float* __restrict__ x,
            const float* __restrict__ w1, const float* __restrict__ b1,
            const float* __restrict__ w2, const float* __restrict__ b2) {
    __shared__ __align__(16) float sx[2][30][32];   // padded input (1920 f)
    __shared__ __align__(16) float sp[2 * SS];      // conv1 pooled out (5184 f)
    __shared__ __align__(16) float sw1p[96];        // conv1 w, [oc][12]
    __shared__ __align__(16) float sw2p[1600];      // conv2 w, [oc]*100 + [ic]*12
    __shared__ __align__(16) float sflat[2 * 784];  // output staging
    __shared__ float sb1[8], sb2[16];

    const int tid = threadIdx.x;
    const int b0 = blockIdx.x * 2;

    for (int i = tid; i < 1920; i += 224) ((float*)sx)[i] = 0.0f;
    for (int i = tid; i < 2 * SS; i += 224) sp[i] = 0.0f;
    for (int i = tid; i < 1152; i += 224) {
        int oc = i / 72, rem = i % 72, ic = rem / 9, j = rem % 9;
        sw2p[oc * 100 + ic * 12 + j] = w2[i];
    }
    if (tid < 72) sw1p[(tid / 9) * 12 + (tid % 9)] = w1[tid];
    if (tid < 8)  sb1[tid] = b1[tid];
    if (tid < 16) sb2[tid] = b2[tid];
    __syncthreads();

    for (int i = tid; i < 2 * 784; i += 224) {
        int s = i / 784, r = i % 784;
        sx[s][r / 28 + 1][r % 28 + 1] = x[(b0 + s) * 784 + r];
    }
    __syncthreads();

    // -------- conv1 (1->8) + relu + pool -> sp --------
    {
        const int oc = tid & 7;
        const int rest = tid >> 3;      // 0..27
        const int y2 = rest % 14;
        const int s = rest / 14;
        float4 wa = *(const float4*)&sw1p[oc * 12];
        float4 wb = *(const float4*)&sw1p[oc * 12 + 4];
        float4 wc = *(const float4*)&sw1p[oc * 12 + 8];
        const float w[9] = {wa.x, wa.y, wa.z, wa.w, wb.x, wb.y, wb.z, wb.w, wc.x};
        const float bias = sb1[oc];
        float* spb = &sp[s * SS + oc * PS + (y2 + 1) * RS];

        #pragma unroll
        for (int xh = 0; xh < 2; xh++) {
            const int SH = xh * 2;
            float a0[14], a1[14];
            #pragma unroll
            for (int i2 = 0; i2 < 14; i2++) { a0[i2] = bias; a1[i2] = bias; }

            #pragma unroll
            for (int r = 0; r < 4; r++) {
                float e[20];
                const float* rp = &sx[s][2 * y2 + r][xh * 12];
                #pragma unroll
                for (int q = 0; q < 5; q++) ((float4*)e)[q] = ((const float4*)rp)[q];
                if (r < 3) {
                    #pragma unroll
                    for (int xx = 0; xx < 14; xx++) {
                        float a = a0[xx];
                        a = fmaf(e[xx + SH],     w[3 * r],     a);
                        a = fmaf(e[xx + SH + 1], w[3 * r + 1], a);
                        a = fmaf(e[xx + SH + 2], w[3 * r + 2], a);
                        a0[xx] = a;
                    }
                }
                if (r >= 1) {
                    #pragma unroll
                    for (int xx = 0; xx < 14; xx++) {
                        float a = a1[xx];
                        a = fmaf(e[xx + SH],     w[3 * (r - 1)],     a);
                        a = fmaf(e[xx + SH + 1], w[3 * (r - 1) + 1], a);
                        a = fmaf(e[xx + SH + 2], w[3 * (r - 1) + 2], a);
                        a1[xx] = a;
                    }
                }
            }
            #pragma unroll
            for (int p = 0; p < 7; p++) {
                float a = fmaxf(a0[2 * p], 0.0f);
                a = fmaxf(a, fmaxf(a0[2 * p + 1], 0.0f));
                a = fmaxf(a, fmaxf(a1[2 * p], 0.0f));
                a = fmaxf(a, fmaxf(a1[2 * p + 1], 0.0f));
                spb[xh * 7 + p + 1] = a;
            }
        }
    }
    __syncthreads();

    // -------- conv2 (8->16) + relu + pool -> sflat -> g_flat --------
    {
        const int oc = tid & 15;
        const int rest = tid >> 4;     // 0..13
        const int y2 = rest % 7;
        const int s = rest / 7;
        const float bias = sb2[oc];
        float acc0[14], acc1[14];
        #pragma unroll
        for (int i2 = 0; i2 < 14; i2++) { acc0[i2] = bias; acc1[i2] = bias; }

        #pragma unroll
        for (int ic = 0; ic < 8; ic++) {
            const float* wp = &sw2p[oc * 100 + ic * 12];
            float4 wa = *(const float4*)(wp);
            float4 wb = *(const float4*)(wp + 4);
            float4 wc = *(const float4*)(wp + 8);
            const float w[9] = {wa.x, wa.y, wa.z, wa.w, wb.x, wb.y, wb.z, wb.w, wc.x};

            const float* rowp = &sp[s * SS + ic * PS + (2 * y2) * RS];
            #pragma unroll
            for (int r = 0; r < 4; r++) {
                float e[16];
                #pragma unroll
                for (int q = 0; q < 4; q++)
                    ((float4*)e)[q] = ((const float4*)(rowp + r * RS))[q];
                if (r < 3) {
                    #pragma unroll
                    for (int xx = 0; xx < 14; xx++) {
                        float a = acc0[xx];
                        a = fmaf(e[xx],     w[3 * r],     a);
                        a = fmaf(e[xx + 1], w[3 * r + 1], a);
                        a = fmaf(e[xx + 2], w[3 * r + 2], a);
                        acc0[xx] = a;
                    }
                }
                if (r >= 1) {
                    #pragma unroll
                    for (int xx = 0; xx < 14; xx++) {
                        float a = acc1[xx];
                        a = fmaf(e[xx],     w[3 * (r - 1)],     a);
                        a = fmaf(e[xx + 1], w[3 * (r - 1) + 1], a);
                        a = fmaf(e[xx + 2], w[3 * (r - 1) + 2], a);
                        acc1[xx] = a;
                    }
                }
            }
        }

        float* stg = &sflat[s * 784 + oc * 49 + y2 * 7];
        #pragma unroll
        for (int p = 0; p < 7; p++) {
            float a = fmaxf(acc0[2 * p], 0.0f);
            a = fmaxf(a, fmaxf(acc0[2 * p + 1], 0.0f));
            a = fmaxf(a, fmaxf(acc1[2 * p], 0.0f));
            a = fmaxf(a, fmaxf(acc1[2 * p + 1], 0.0f));
            stg[p] = a;
        }
    }
    __syncthreads();

    {
        float4* dst = (float4*)&g_flat[b0 * 784];
        const float4* src = (const float4*)sflat;
        for (int i = tid; i < 392; i += 224) dst[i] = src[i];
    }
}

// ---------------------------------------------------------------------------
// K2: FC1(784->64)+relu + FC2(64->4). 64 samples/block, 128 threads,
// 4 outputs x 8 samples register tile -> FMA-bound inner loop (128 FMA per
// 12 LDS.128).
// ---------------------------------------------------------------------------
#define FCS 60
__global__ __launch_bounds__(128)
void k_fc(const float* __restrict__ fc1_w, const float* __restrict__ fc1_b,
          const float* __restrict__ fc2_w, const float* __restrict__ fc2_b) {
    __shared__ __align__(16) float sAW[2 * 64 * FCS];  // sA[64*60] | sW[64*60]
    __shared__ float sw2[256];
    float* sA = sAW;
    float* sW = sAW + 64 * FCS;

    const int tid = threadIdx.x;
    const int s0 = blockIdx.x * 64;
    const int jo = tid & 15;     // outputs {jo, jo+16, jo+32, jo+48}
    const int sg = tid >> 4;     // 0..7 -> samples sg*8 .. sg*8+7

    sw2[tid] = fc2_w[tid];
    sw2[tid + 128] = fc2_w[tid + 128];

    float acc[4][8];
    #pragma unroll
    for (int m = 0; m < 4; m++)
        #pragma unroll
        for (int u = 0; u < 8; u++) acc[m][u] = 0.0f;

    for (int kt = 0; kt < 784; kt += 56) {
        __syncthreads();
        #pragma unroll
        for (int i = tid; i < 64 * 14; i += 128) {
            int r = i / 14, q = i % 14;
            ((float4*)&sA[r * FCS])[q] =
                *(const float4*)&g_flat[(s0 + r) * 784 + kt + q * 4];
            ((float4*)&sW[r * FCS])[q] =
                *(const float4*)&fc1_w[r * 784 + kt + q * 4];
        }
        __syncthreads();
        #pragma unroll
        for (int k4 = 0; k4 < 14; k4++) {
            float4 w0 = *(const float4*)&sW[jo * FCS + k4 * 4];
            float4 w1 = *(const float4*)&sW[(jo + 16) * FCS + k4 * 4];
            float4 w2v = *(const float4*)&sW[(jo + 32) * FCS + k4 * 4];
            float4 w3 = *(const float4*)&sW[(jo + 48) * FCS + k4 * 4];
            #pragma unroll
            for (int u = 0; u < 8; u++) {
                float4 a = *(const float4*)&sA[(sg * 8 + u) * FCS + k4 * 4];
                acc[0][u] = fmaf(a.x, w0.x, acc[0][u]);
                acc[0][u] = fmaf(a.y, w0.y, acc[0][u]);
                acc[0][u] = fmaf(a.z, w0.z, acc[0][u]);
                acc[0][u] = fmaf(a.w, w0.w, acc[0][u]);
                acc[1][u] = fmaf(a.x, w1.x, acc[1][u]);
                acc[1][u] = fmaf(a.y, w1.y, acc[1][u]);
                acc[1][u] = fmaf(a.z, w1.z, acc[1][u]);
                acc[1][u] = fmaf(a.w, w1.w, acc[1][u]);
                acc[2][u] = fmaf(a.x, w2v.x, acc[2][u]);
                acc[2][u] = fmaf(a.y, w2v.y, acc[2][u]);
                acc[2][u] = fmaf(a.z, w2v.z, acc[2][u]);
                acc[2][u] = fmaf(a.w, w2v.w, acc[2][u]);
                acc[3][u] = fmaf(a.x, w3.x, acc[3][u]);
                acc[3][u] = fmaf(a.y, w3.y, acc[3][u]);
                acc[3][u] = fmaf(a.z, w3.z, acc[3][u]);
                acc[3][u] = fmaf(a.w, w3.w, acc[3][u]);
            }
        }
    }

    __syncthreads();
    float* sh = sAW;   // reuse: 64 samples x stride 65 = 4160 floats
    #pragma unroll
    for (int m = 0; m < 4; m++) {
        const float bj = fc1_b[jo + 16 * m];
        #pragma unroll
        for (int u = 0; u < 8; u++)
            sh[(sg * 8 + u) * 65 + jo + 16 * m] = fmaxf(acc[m][u] + bj, 0.0f);
    }
    __syncthreads();

    // FC2: 64 samples x 4 channels = 256 work items, 128 threads -> 2 each
    #pragma unroll
    for (int base = 0; base < 256; base += 128) {
        const int idx = base + tid;
        const int s = idx >> 2, c = idx & 3;
        float a = fc2_b[c];
        const float* hp = &sh[s * 65];
        const float* wc = &sw2[c * 64];
        #pragma unroll
        for (int j = 0; j < 64; j++) a = fmaf(hp[j], wc[j], a);
        g_feat[(s0 + s) * 4 + c] = a;
    }
}

// ---------------------------------------------------------------------------
// K3: batch mean/var -> scale/shift
// ---------------------------------------------------------------------------
__global__ void k_stats(const float* __restrict__ bn_g,
                        const float* __restrict__ bn_b) {
    __shared__ double ss[256][8];
    const int tid = threadIdx.x;
    double sum[4] = {0, 0, 0, 0}, sq[4] = {0, 0, 0, 0};
    for (int s = tid; s < BATCH; s += 256) {
        float4 f = ((const float4*)g_feat)[s];
        double v;
        v = (double)f.x; sum[0] += v; sq[0] += v * v;
        v = (double)f.y; sum[1] += v; sq[1] += v * v;
        v = (double)f.z; sum[2] += v; sq[2] += v * v;
        v = (double)f.w; sum[3] += v; sq[3] += v * v;
    }
    #pragma unroll
    for (int c = 0; c < 4; c++) { ss[tid][c] = sum[c]; ss[tid][4 + c] = sq[c]; }
    __syncthreads();
    for (int off = 128; off >= 1; off >>= 1) {
        if (tid < off) {
            #pragma unroll
            for (int k = 0; k < 8; k++) ss[tid][k] += ss[tid + off][k];
        }
        __syncthreads();
    }
    if (tid < 4) {
        double m = ss[0][tid] / (double)BATCH;
        double var = ss[0][4 + tid] / (double)BATCH - m * m;
        float scale = (float)((double)bn_g[tid] / sqrt(var + 1e-5));
        float shift = bn_b[tid] - (float)m * scale;
        g_scsh[tid] = scale;
        g_scsh[4 + tid] = shift;
    }
}

// ---------------------------------------------------------------------------
// K4: quantum state-vector sim + PauliZ measurement
// ---------------------------------------------------------------------------
template <int STR>
__device__ __forceinline__ void rot_rx(float* sr, float* si, float c, float s) {
    #pragma unroll
    for (int k = 0; k < 16; k++) {
        if (k & STR) continue;
        int k1 = k | STR;
        float ar0 = sr[k], ai0 = si[k], ar1 = sr[k1], ai1 = si[k1];
        sr[k]  = c * ar0 + s * ai1;
        si[k]  = c * ai0 - s * ar1;
        sr[k1] = s * ai0 + c * ar1;
        si[k1] = -s * ar0 + c * ai1;
    }
}

template <int STR>
__device__ __forceinline__ void rot_ry(float* sr, float* si, float c, float s) {
    #pragma unroll
    for (int k = 0; k < 16; k++) {
        if (k & STR) continue;
        int k1 = k | STR;
        float ar0 = sr[k], ai0 = si[k], ar1 = sr[k1], ai1 = si[k1];
        sr[k]  = c * ar0 - s * ar1;
        si[k]  = c * ai0 - s * ai1;
        sr[k1] = s * ar0 + c * ar1;
        si[k1] = s * ai0 + c * ai1;
    }
}

template <int STR>
__device__ __forceinline__ void rot_rz(float* sr, float* si, float c, float s) {
    #pragma unroll
    for (int k = 0; k < 16; k++) {
        float ar = sr[k], ai = si[k];
        if (k & STR) { sr[k] = c * ar - s * ai; si[k] = c * ai + s * ar; }
        else         { sr[k] = c * ar + s * ai; si[k] = c * ai - s * ar; }
    }
}

__device__ __forceinline__ void cnot_c3_t0(float* sr, float* si) {
    #pragma unroll
    for (int k = 1; k < 8; k += 2) {
        int k1 = k | 8;
        float tr = sr[k], ti = si[k];
        sr[k] = sr[k1]; si[k] = si[k1];
        sr[k1] = tr;    si[k1] = ti;
    }
}

__global__ void k_quantum(const float* __restrict__ rl_params,
                          float* __restrict__ out) {
    __shared__ float gc[23], gs[23];
    const int tid = threadIdx.x;
    if (tid < 23) {
        float t = rl_params[tid] * 0.5f;
        gc[tid] = cosf(t);
        gs[tid] = sinf(t);
    }
    __syncthreads();

    const int b = blockIdx.x * blockDim.x + tid;
    if (b >= BATCH) return;

    float sr[16], si[16];
    #pragma unroll
    for (int k = 0; k < 16; k++) { sr[k] = 0.0f; si[k] = 0.0f; }
    sr[0] = 1.0f;

    float4 f4 = ((const float4*)g_feat)[b];
    {
        float f, s, c;
        f = (f4.x * g_scsh[0] + g_scsh[4]) * 0.5f; s = sinf(f); c = cosf(f);
        rot_rx<8>(sr, si, c, s);
        f = (f4.y * g_scsh[1] + g_scsh[5]) * 0.5f; s = sinf(f); c = cosf(f);
        rot_rx<4>(sr, si, c, s);
        f = (f4.z * g_scsh[2] + g_scsh[6]) * 0.5f; s = sinf(f); c = cosf(f);
        rot_rx<2>(sr, si, c, s);
        f = (f4.w * g_scsh[3] + g_scsh[7]) * 0.5f; s = sinf(f); c = cosf(f);
        rot_rx<1>(sr, si, c, s);
    }

    #pragma unroll
    for (int r = 0; r < 7; r++) {
        rot_rx<8>(sr, si, gc[3 * r],     gs[3 * r]);
        rot_ry<4>(sr, si, gc[3 * r + 1], gs[3 * r + 1]);
        rot_rz<2>(sr, si, gc[3 * r + 2], gs[3 * r + 2]);
        cnot_c3_t0(sr, si);
    }
    rot_rx<8>(sr, si, gc[21], gs[21]);
    rot_ry<4>(sr, si, gc[22], gs[22]);

    float p[16];
    #pragma unroll
    for (int k = 0; k < 16; k++) p[k] = sr[k] * sr[k] + si[k] * si[k];
    #pragma unroll
    for (int w = 0; w < 4; w++) {
        int str = 8 >> w;
        float acc = 0.0f;
        #pragma unroll
        for (int k = 0; k < 16; k++) acc += (k & str) ? -p[k] : p[k];
        out[b * 4 + w] = acc;
    }
}

// ---------------------------------------------------------------------------
// Launch
// ---------------------------------------------------------------------------
extern "C" void kernel_launch(void* const* d_in, const int* in_sizes, int n_in,
                              void* d_out, int out_size) {
    const float* x       = (const float*)d_in[0];
    const float* conv1_w = (const float*)d_in[1];
    const float* conv1_b = (const float*)d_in[2];
    const float* conv2_w = (const float*)d_in[3];
    const float* conv2_b = (const float*)d_in[4];
    const float* fc1_w   = (const float*)d_in[5];
    const float* fc1_b   = (const float*)d_in[6];
    const float* fc2_w   = (const float*)d_in[7];
    const float* fc2_b   = (const float*)d_in[8];
    const float* bn_g    = (const float*)d_in[9];
    const float* bn_b    = (const float*)d_in[10];
    const float* rl      = (const float*)d_in[11];
    float* out = (float*)d_out;

    k_conv<<<BATCH / 2, 224>>>(x, conv1_w, conv1_b, conv2_w, conv2_b);
    k_fc<<<BATCH / 64, 128>>>(fc1_w, fc1_b, fc2_w, fc2_b);
    k_stats<<<1, 256>>>(bn_g, bn_b);
    k_quantum<<<BATCH / 256, 256>>>(rl, out);
}

// round 12
// speedup vs baseline: 1.5461x; 1.0231x over previous
#include <cuda_runtime.h>
#include <math.h>

#define BATCH 8192

// sp layout constants (bank-conflict-free padded layout)
#define RS 20            // row stride in floats
#define PS 324           // plane (channel) stride
#define SS (8 * PS)      // sample stride: 2592 floats

// ---------------------------------------------------------------------------
// Scratch
// ---------------------------------------------------------------------------
__device__ __align__(16) float g_flat[BATCH * 784]; // conv2 output [B,784]
__device__ __align__(16) float g_feat[BATCH * 4];   // fc2 output   [B,4]
__device__ float g_scsh[8];                         // [scale, shift]

// ---------------------------------------------------------------------------
// K1: fused conv1+pool, conv2+pool. 2 samples/block, 224 threads (R7-proven,
// at the scalar-FFMA wall). All inner loads LDS.128; coalesced STG.128 out.
// ---------------------------------------------------------------------------
__global__ __launch_bounds__(224, 4)
void k_conv(const float* __restrict__ x,
            const float* __restrict__ w1, const float* __restrict__ b1,
            const float* __restrict__ w2, const float* __restrict__ b2) {
    __shared__ __align__(16) float sx[2][30][32];   // padded input (1920 f)
    __shared__ __align__(16) float sp[2 * SS];      // conv1 pooled out (5184 f)
    __shared__ __align__(16) float sw1p[96];        // conv1 w, [oc][12]
    __shared__ __align__(16) float sw2p[1600];      // conv2 w, [oc]*100 + [ic]*12
    __shared__ __align__(16) float sflat[2 * 784];  // output staging
    __shared__ float sb1[8], sb2[16];

    const int tid = threadIdx.x;
    const int b0 = blockIdx.x * 2;

    for (int i = tid; i < 1920; i += 224) ((float*)sx)[i] = 0.0f;
    for (int i = tid; i < 2 * SS; i += 224) sp[i] = 0.0f;
    for (int i = tid; i < 1152; i += 224) {
        int oc = i / 72, rem = i % 72, ic = rem / 9, j = rem % 9;
        sw2p[oc * 100 + ic * 12 + j] = w2[i];
    }
    if (tid < 72) sw1p[(tid / 9) * 12 + (tid % 9)] = w1[tid];
    if (tid < 8)  sb1[tid] = b1[tid];
    if (tid < 16) sb2[tid] = b2[tid];
    __syncthreads();

    for (int i = tid; i < 2 * 784; i += 224) {
        int s = i / 784, r = i % 784;
        sx[s][r / 28 + 1][r % 28 + 1] = x[(b0 + s) * 784 + r];
    }
    __syncthreads();

    // -------- conv1 (1->8) + relu + pool -> sp --------
    {
        const int oc = tid & 7;
        const int rest = tid >> 3;      // 0..27
        const int y2 = rest % 14;
        const int s = rest / 14;
        float4 wa = *(const float4*)&sw1p[oc * 12];
        float4 wb = *(const float4*)&sw1p[oc * 12 + 4];
        float4 wc = *(const float4*)&sw1p[oc * 12 + 8];
        const float w[9] = {wa.x, wa.y, wa.z, wa.w, wb.x, wb.y, wb.z, wb.w, wc.x};
        const float bias = sb1[oc];
        float* spb = &sp[s * SS + oc * PS + (y2 + 1) * RS];

        #pragma unroll
        for (int xh = 0; xh < 2; xh++) {
            const int SH = xh * 2;
            float a0[14], a1[14];
            #pragma unroll
            for (int i2 = 0; i2 < 14; i2++) { a0[i2] = bias; a1[i2] = bias; }

            #pragma unroll
            for (int r = 0; r < 4; r++) {
                float e[20];
                const float* rp = &sx[s][2 * y2 + r][xh * 12];
                #pragma unroll
                for (int q = 0; q < 5; q++) ((float4*)e)[q] = ((const float4*)rp)[q];
                if (r < 3) {
                    #pragma unroll
                    for (int xx = 0; xx < 14; xx++) {
                        float a = a0[xx];
                        a = fmaf(e[xx + SH],     w[3 * r],     a);
                        a = fmaf(e[xx + SH + 1], w[3 * r + 1], a);
                        a = fmaf(e[xx + SH + 2], w[3 * r + 2], a);
                        a0[xx] = a;
                    }
                }
                if (r >= 1) {
                    #pragma unroll
                    for (int xx = 0; xx < 14; xx++) {
                        float a = a1[xx];
                        a = fmaf(e[xx + SH],     w[3 * (r - 1)],     a);
                        a = fmaf(e[xx + SH + 1], w[3 * (r - 1) + 1], a);
                        a = fmaf(e[xx + SH + 2], w[3 * (r - 1) + 2], a);
                        a1[xx] = a;
                    }
                }
            }
            #pragma unroll
            for (int p = 0; p < 7; p++) {
                float a = fmaxf(a0[2 * p], 0.0f);
                a = fmaxf(a, fmaxf(a0[2 * p + 1], 0.0f));
                a = fmaxf(a, fmaxf(a1[2 * p], 0.0f));
                a = fmaxf(a, fmaxf(a1[2 * p + 1], 0.0f));
                spb[xh * 7 + p + 1] = a;
            }
        }
    }
    __syncthreads();

    // -------- conv2 (8->16) + relu + pool -> sflat -> g_flat --------
    {
        const int oc = tid & 15;
        const int rest = tid >> 4;     // 0..13
        const int y2 = rest % 7;
        const int s = rest / 7;
        const float bias = sb2[oc];
        float acc0[14], acc1[14];
        #pragma unroll
        for (int i2 = 0; i2 < 14; i2++) { acc0[i2] = bias; acc1[i2] = bias; }

        #pragma unroll
        for (int ic = 0; ic < 8; ic++) {
            const float* wp = &sw2p[oc * 100 + ic * 12];
            float4 wa = *(const float4*)(wp);
            float4 wb = *(const float4*)(wp + 4);
            float4 wc = *(const float4*)(wp + 8);
            const float w[9] = {wa.x, wa.y, wa.z, wa.w, wb.x, wb.y, wb.z, wb.w, wc.x};

            const float* rowp = &sp[s * SS + ic * PS + (2 * y2) * RS];
            #pragma unroll
            for (int r = 0; r < 4; r++) {
                float e[16];
                #pragma unroll
                for (int q = 0; q < 4; q++)
                    ((float4*)e)[q] = ((const float4*)(rowp + r * RS))[q];
                if (r < 3) {
                    #pragma unroll
                    for (int xx = 0; xx < 14; xx++) {
                        float a = acc0[xx];
                        a = fmaf(e[xx],     w[3 * r],     a);
                        a = fmaf(e[xx + 1], w[3 * r + 1], a);
                        a = fmaf(e[xx + 2], w[3 * r + 2], a);
                        acc0[xx] = a;
                    }
                }
                if (r >= 1) {
                    #pragma unroll
                    for (int xx = 0; xx < 14; xx++) {
                        float a = acc1[xx];
                        a = fmaf(e[xx],     w[3 * (r - 1)],     a);
                        a = fmaf(e[xx + 1], w[3 * (r - 1) + 1], a);
                        a = fmaf(e[xx + 2], w[3 * (r - 1) + 2], a);
                        acc1[xx] = a;
                    }
                }
            }
        }

        float* stg = &sflat[s * 784 + oc * 49 + y2 * 7];
        #pragma unroll
        for (int p = 0; p < 7; p++) {
            float a = fmaxf(acc0[2 * p], 0.0f);
            a = fmaxf(a, fmaxf(acc0[2 * p + 1], 0.0f));
            a = fmaxf(a, fmaxf(acc1[2 * p], 0.0f));
            a = fmaxf(a, fmaxf(acc1[2 * p + 1], 0.0f));
            stg[p] = a;
        }
    }
    __syncthreads();

    {
        float4* dst = (float4*)&g_flat[b0 * 784];
        const float4* src = (const float4*)sflat;
        for (int i = tid; i < 392; i += 224) dst[i] = src[i];
    }
}

// ---------------------------------------------------------------------------
// K2: FC1(784->64)+relu + FC2(64->4), tiled GEMM. 64 samples/block,
// 256 threads (R6-proven shape) + register-prefetch pipeline: next k-tile's
// global loads are in flight during current tile's FMAs.
// ---------------------------------------------------------------------------
#define FCS 60
__global__ __launch_bounds__(256)
void k_fc(const float* __restrict__ fc1_w, const float* __restrict__ fc1_b,
          const float* __restrict__ fc2_w, const float* __restrict__ fc2_b) {
    __shared__ __align__(16) float sAW[2 * 64 * FCS];  // sA[64*60] | sW[64*60]
    __shared__ float sw2[256];

    const int tid = threadIdx.x;
    const int s0 = blockIdx.x * 64;
    const int jj = tid & 31;     // output pair {jj, jj+32}
    const int ss = tid >> 5;     // sample group: samples ss*8 .. ss*8+7
    const float* sW = sAW + 64 * FCS;

    sw2[tid] = fc2_w[tid];

    // per-thread staging plan: 7 float4 per tile (1792 total = 2 x 64 x 14)
    const float* src[7];
    int dst[7];
    #pragma unroll
    for (int j = 0; j < 7; j++) {
        int i = tid + 256 * j;
        if (i < 896) {
            int r = i / 14, q = i % 14;
            src[j] = &g_flat[(s0 + r) * 784 + q * 4];
            dst[j] = r * FCS + q * 4;
        } else {
            int i2 = i - 896;
            int r = i2 / 14, q = i2 % 14;
            src[j] = &fc1_w[r * 784 + q * 4];
            dst[j] = 64 * FCS + r * FCS + q * 4;
        }
    }

    float4 pf[7];
    #pragma unroll
    for (int j = 0; j < 7; j++) { pf[j] = *(const float4*)src[j]; src[j] += 56; }

    float acc[2][8];
    #pragma unroll
    for (int u = 0; u < 8; u++) { acc[0][u] = 0.0f; acc[1][u] = 0.0f; }

    for (int t = 0; t < 14; t++) {
        __syncthreads();
        #pragma unroll
        for (int j = 0; j < 7; j++) *(float4*)&sAW[dst[j]] = pf[j];
        __syncthreads();
        if (t < 13) {
            #pragma unroll
            for (int j = 0; j < 7; j++) { pf[j] = *(const float4*)src[j]; src[j] += 56; }
        }
        #pragma unroll
        for (int k4 = 0; k4 < 14; k4++) {
            float4 w0 = *(const float4*)&sW[jj * FCS + k4 * 4];
            float4 w1 = *(const float4*)&sW[(jj + 32) * FCS + k4 * 4];
            #pragma unroll
            for (int u = 0; u < 8; u++) {
                float4 a = *(const float4*)&sAW[(ss * 8 + u) * FCS + k4 * 4];
                float t0 = acc[0][u], t1 = acc[1][u];
                t0 = fmaf(a.x, w0.x, t0); t1 = fmaf(a.x, w1.x, t1);
                t0 = fmaf(a.y, w0.y, t0); t1 = fmaf(a.y, w1.y, t1);
                t0 = fmaf(a.z, w0.z, t0); t1 = fmaf(a.z, w1.z, t1);
                t0 = fmaf(a.w, w0.w, t0); t1 = fmaf(a.w, w1.w, t1);
                acc[0][u] = t0; acc[1][u] = t1;
            }
        }
    }

    __syncthreads();
    float* sh = sAW;   // reuse: 64 samples x stride 65
    const float bj0 = fc1_b[jj], bj1 = fc1_b[jj + 32];
    #pragma unroll
    for (int u = 0; u < 8; u++) {
        sh[(ss * 8 + u) * 65 + jj]      = fmaxf(acc[0][u] + bj0, 0.0f);
        sh[(ss * 8 + u) * 65 + jj + 32] = fmaxf(acc[1][u] + bj1, 0.0f);
    }
    __syncthreads();

    {
        const int s = tid >> 2, c = tid & 3;
        float a = fc2_b[c];
        const float* hp = &sh[s * 65];
        const float* wc = &sw2[c * 64];
        #pragma unroll
        for (int j = 0; j < 64; j++) a = fmaf(hp[j], wc[j], a);
        g_feat[(s0 + s) * 4 + c] = a;
    }
}

// ---------------------------------------------------------------------------
// K3: batch mean/var -> scale/shift
// ---------------------------------------------------------------------------
__global__ void k_stats(const float* __restrict__ bn_g,
                        const float* __restrict__ bn_b) {
    __shared__ double ss[256][8];
    const int tid = threadIdx.x;
    double sum[4] = {0, 0, 0, 0}, sq[4] = {0, 0, 0, 0};
    for (int s = tid; s < BATCH; s += 256) {
        float4 f = ((const float4*)g_feat)[s];
        double v;
        v = (double)f.x; sum[0] += v; sq[0] += v * v;
        v = (double)f.y; sum[1] += v; sq[1] += v * v;
        v = (double)f.z; sum[2] += v; sq[2] += v * v;
        v = (double)f.w; sum[3] += v; sq[3] += v * v;
    }
    #pragma unroll
    for (int c = 0; c < 4; c++) { ss[tid][c] = sum[c]; ss[tid][4 + c] = sq[c]; }
    __syncthreads();
    for (int off = 128; off >= 1; off >>= 1) {
        if (tid < off) {
            #pragma unroll
            for (int k = 0; k < 8; k++) ss[tid][k] += ss[tid + off][k];
        }
        __syncthreads();
    }
    if (tid < 4) {
        double m = ss[0][tid] / (double)BATCH;
        double var = ss[0][4 + tid] / (double)BATCH - m * m;
        float scale = (float)((double)bn_g[tid] / sqrt(var + 1e-5));
        float shift = bn_b[tid] - (float)m * scale;
        g_scsh[tid] = scale;
        g_scsh[4 + tid] = shift;
    }
}

// ---------------------------------------------------------------------------
// K4: quantum state-vector sim + PauliZ measurement
// ---------------------------------------------------------------------------
template <int STR>
__device__ __forceinline__ void rot_rx(float* sr, float* si, float c, float s) {
    #pragma unroll
    for (int k = 0; k < 16; k++) {
        if (k & STR) continue;
        int k1 = k | STR;
        float ar0 = sr[k], ai0 = si[k], ar1 = sr[k1], ai1 = si[k1];
        sr[k]  = c * ar0 + s * ai1;
        si[k]  = c * ai0 - s * ar1;
        sr[k1] = s * ai0 + c * ar1;
        si[k1] = -s * ar0 + c * ai1;
    }
}

template <int STR>
__device__ __forceinline__ void rot_ry(float* sr, float* si, float c, float s) {
    #pragma unroll
    for (int k = 0; k < 16; k++) {
        if (k & STR) continue;
        int k1 = k | STR;
        float ar0 = sr[k], ai0 = si[k], ar1 = sr[k1], ai1 = si[k1];
        sr[k]  = c * ar0 - s * ar1;
        si[k]  = c * ai0 - s * ai1;
        sr[k1] = s * ar0 + c * ar1;
        si[k1] = s * ai0 + c * ai1;
    }
}

template <int STR>
__device__ __forceinline__ void rot_rz(float* sr, float* si, float c, float s) {
    #pragma unroll
    for (int k = 0; k < 16; k++) {
        float ar = sr[k], ai = si[k];
        if (k & STR) { sr[k] = c * ar - s * ai; si[k] = c * ai + s * ar; }
        else         { sr[k] = c * ar + s * ai; si[k] = c * ai - s * ar; }
    }
}

__device__ __forceinline__ void cnot_c3_t0(float* sr, float* si) {
    #pragma unroll
    for (int k = 1; k < 8; k += 2) {
        int k1 = k | 8;
        float tr = sr[k], ti = si[k];
        sr[k] = sr[k1]; si[k] = si[k1];
        sr[k1] = tr;    si[k1] = ti;
    }
}

__global__ void k_quantum(const float* __restrict__ rl_params,
                          float* __restrict__ out) {
    __shared__ float gc[23], gs[23];
    const int tid = threadIdx.x;
    if (tid < 23) {
        float t = rl_params[tid] * 0.5f;
        gc[tid] = cosf(t);
        gs[tid] = sinf(t);
    }
    __syncthreads();

    const int b = blockIdx.x * blockDim.x + tid;
    if (b >= BATCH) return;

    float sr[16], si[16];
    #pragma unroll
    for (int k = 0; k < 16; k++) { sr[k] = 0.0f; si[k] = 0.0f; }
    sr[0] = 1.0f;

    float4 f4 = ((const float4*)g_feat)[b];
    {
        float f, s, c;
        f = (f4.x * g_scsh[0] + g_scsh[4]) * 0.5f; s = sinf(f); c = cosf(f);
        rot_rx<8>(sr, si, c, s);
        f = (f4.y * g_scsh[1] + g_scsh[5]) * 0.5f; s = sinf(f); c = cosf(f);
        rot_rx<4>(sr, si, c, s);
        f = (f4.z * g_scsh[2] + g_scsh[6]) * 0.5f; s = sinf(f); c = cosf(f);
        rot_rx<2>(sr, si, c, s);
        f = (f4.w * g_scsh[3] + g_scsh[7]) * 0.5f; s = sinf(f); c = cosf(f);
        rot_rx<1>(sr, si, c, s);
    }

    #pragma unroll
    for (int r = 0; r < 7; r++) {
        rot_rx<8>(sr, si, gc[3 * r],     gs[3 * r]);
        rot_ry<4>(sr, si, gc[3 * r + 1], gs[3 * r + 1]);
        rot_rz<2>(sr, si, gc[3 * r + 2], gs[3 * r + 2]);
        cnot_c3_t0(sr, si);
    }
    rot_rx<8>(sr, si, gc[21], gs[21]);
    rot_ry<4>(sr, si, gc[22], gs[22]);

    float p[16];
    #pragma unroll
    for (int k = 0; k < 16; k++) p[k] = sr[k] * sr[k] + si[k] * si[k];
    #pragma unroll
    for (int w = 0; w < 4; w++) {
        int str = 8 >> w;
        float acc = 0.0f;
        #pragma unroll
        for (int k = 0; k < 16; k++) acc += (k & str) ? -p[k] : p[k];
        out[b * 4 + w] = acc;
    }
}

// ---------------------------------------------------------------------------
// Launch
// ---------------------------------------------------------------------------
extern "C" void kernel_launch(void* const* d_in, const int* in_sizes, int n_in,
                              void* d_out, int out_size) {
    const float* x       = (const float*)d_in[0];
    const float* conv1_w = (const float*)d_in[1];
    const float* conv1_b = (const float*)d_in[2];
    const float* conv2_w = (const float*)d_in[3];
    const float* conv2_b = (const float*)d_in[4];
    const float* fc1_w   = (const float*)d_in[5];
    const float* fc1_b   = (const float*)d_in[6];
    const float* fc2_w   = (const float*)d_in[7];
    const float* fc2_b   = (const float*)d_in[8];
    const float* bn_g    = (const float*)d_in[9];
    const float* bn_b    = (const float*)d_in[10];
    const float* rl      = (const float*)d_in[11];
    float* out = (float*)d_out;

    k_conv<<<BATCH / 2, 224>>>(x, conv1_w, conv1_b, conv2_w, conv2_b);
    k_fc<<<BATCH / 64, 256>>>(fc1_w, fc1_b, fc2_w, fc2_b);
    k_stats<<<1, 256>>>(bn_g, bn_b);
    k_quantum<<<BATCH / 256, 256>>>(rl, out);
}